// round 1
// baseline (speedup 1.0000x reference)
#include <cuda_runtime.h>
#include <math.h>

#define N_VARS 50000
#define HID 128
#define N_EDGES 400000
#define NP 50048            // padded to multiple of 64
#define STEPS 4
#define BN_EPS 1e-5f

// ---------------- scratch (static device memory; no allocation) ----------------
__device__ float g_hA[NP * HID];
__device__ float g_hB[NP * HID];
__device__ float g_c[NP * HID];
__device__ float g_agg[NP * HID];
__device__ float g_rec[NP * HID];
__device__ float g_degf[NP];
__device__ float g_Wp1[256 * HID];        // [k][j]      : transposed W_msg
__device__ float g_Wp2[256 * 4 * HID];    // [k][j][gate]: fused W_ih|W_hh, permuted
__device__ float g_bias[4 * HID];         // b_ih + b_hh
__device__ float g_stats[2 * HID];        // col sums / sumsq of rec
__device__ float g_bnA[HID];
__device__ float g_bnB[HID];

__device__ __forceinline__ float sigf(float x) { return 1.0f / (1.0f + expf(-x)); }

// ---------------- one-time prep: weight permutations + fused bias ----------------
__global__ void prep_kernel(const float* __restrict__ W_msg,
                            const float* __restrict__ W_ih,
                            const float* __restrict__ W_hh,
                            const float* __restrict__ b_ih,
                            const float* __restrict__ b_hh) {
    int t = blockIdx.x * blockDim.x + threadIdx.x;
    int stride = gridDim.x * blockDim.x;
    // Wp1[k*128 + j] = W_msg[j][k]   (k in [0,256), j in [0,128))
    for (int i = t; i < 256 * HID; i += stride) {
        int k = i >> 7, j = i & 127;
        g_Wp1[i] = W_msg[j * 256 + k];
    }
    // Wp2[k*512 + j*4 + g] = (k<128 ? W_ih : W_hh)[g*128 + j][k mod 128]
    for (int i = t; i < 256 * 512; i += stride) {
        int k = i >> 9, r = i & 511;
        int j = r >> 2, g = r & 3;
        int wrow = g * HID + j;
        g_Wp2[i] = (k < HID) ? W_ih[wrow * HID + k] : W_hh[wrow * HID + (k - HID)];
    }
    for (int i = t; i < 4 * HID; i += stride) g_bias[i] = b_ih[i] + b_hh[i];
}

// ---------------- degree (float counts; exact for small ints) ----------------
__global__ void deg_kernel(const int* __restrict__ ei) {
    int i = blockIdx.x * blockDim.x + threadIdx.x;
    if (i < 2 * N_EDGES) atomicAdd(&g_degf[ei[i]], 1.0f);
}

// ---------------- edge aggregation: agg[v] = sum_{(u->v)} h[u] ----------------
__global__ void agg_kernel(const int* __restrict__ ei, const float* __restrict__ hin) {
    int w = (blockIdx.x * blockDim.x + threadIdx.x) >> 5;  // one warp per undirected edge
    int lane = threadIdx.x & 31;
    if (w >= N_EDGES) return;
    int a = ei[w];
    int b = ei[N_EDGES + w];
    int c4 = lane * 4;
    float4 ha = *(const float4*)&hin[(size_t)a * HID + c4];
    float4 hb = *(const float4*)&hin[(size_t)b * HID + c4];
    float* pb = &g_agg[(size_t)b * HID + c4];
    atomicAdd(pb + 0, ha.x); atomicAdd(pb + 1, ha.y);
    atomicAdd(pb + 2, ha.z); atomicAdd(pb + 3, ha.w);
    float* pa = &g_agg[(size_t)a * HID + c4];
    atomicAdd(pa + 0, hb.x); atomicAdd(pa + 1, hb.y);
    atomicAdd(pa + 2, hb.z); atomicAdd(pa + 3, hb.w);
}

// ---------------- GEMM1: rec = ([agg | deg*h] @ Wp1) * var_reg, + col stats ----------------
__global__ void __launch_bounds__(256) rec_gemm(const float* __restrict__ hin,
                                                const float* __restrict__ var_reg) {
    __shared__ __align__(16) float Xs[64][32];
    __shared__ __align__(16) float Ws[32][128];
    const int tid = threadIdx.x;
    const int tx = tid & 31, ty = tid >> 5;
    const int rowBase = blockIdx.x * 64;
    float acc[8][4];
#pragma unroll
    for (int i = 0; i < 8; i++)
#pragma unroll
        for (int c = 0; c < 4; c++) acc[i][c] = 0.f;

    for (int k0 = 0; k0 < 256; k0 += 32) {
#pragma unroll
        for (int t = tid; t < 512; t += 256) {          // 64 rows x 8 float4
            int r = t >> 3, kq = t & 7;
            int row = rowBase + r;
            int gk = k0 + kq * 4;
            float4 v;
            if (gk < HID) {
                v = *(const float4*)&g_agg[(size_t)row * HID + gk];
            } else {
                v = *(const float4*)&hin[(size_t)row * HID + (gk - HID)];
                float d = g_degf[row];
                v.x *= d; v.y *= d; v.z *= d; v.w *= d;
            }
            *(float4*)&Xs[r][kq * 4] = v;
        }
#pragma unroll
        for (int t = tid; t < 1024; t += 256) {         // 32 kk x 32 float4
            int kk = t >> 5, jq = t & 31;
            *(float4*)&Ws[kk][jq * 4] = *(const float4*)&g_Wp1[(k0 + kk) * HID + jq * 4];
        }
        __syncthreads();
#pragma unroll
        for (int kq = 0; kq < 8; ++kq) {
            float4 w0 = *(float4*)&Ws[kq * 4 + 0][tx * 4];
            float4 w1 = *(float4*)&Ws[kq * 4 + 1][tx * 4];
            float4 w2 = *(float4*)&Ws[kq * 4 + 2][tx * 4];
            float4 w3 = *(float4*)&Ws[kq * 4 + 3][tx * 4];
#pragma unroll
            for (int i = 0; i < 8; ++i) {
                float4 x = *(float4*)&Xs[ty * 8 + i][kq * 4];
                acc[i][0] = fmaf(x.x, w0.x, fmaf(x.y, w1.x, fmaf(x.z, w2.x, fmaf(x.w, w3.x, acc[i][0]))));
                acc[i][1] = fmaf(x.x, w0.y, fmaf(x.y, w1.y, fmaf(x.z, w2.y, fmaf(x.w, w3.y, acc[i][1]))));
                acc[i][2] = fmaf(x.x, w0.z, fmaf(x.y, w1.z, fmaf(x.z, w2.z, fmaf(x.w, w3.z, acc[i][2]))));
                acc[i][3] = fmaf(x.x, w0.w, fmaf(x.y, w1.w, fmaf(x.z, w2.w, fmaf(x.w, w3.w, acc[i][3]))));
            }
        }
        __syncthreads();
    }
    float s[4] = {0, 0, 0, 0}, s2[4] = {0, 0, 0, 0};
#pragma unroll
    for (int i = 0; i < 8; i++) {
        int row = rowBase + ty * 8 + i;
        float vr = (row < N_VARS) ? var_reg[row] : 0.f;   // pad rows -> 0 (no stat pollution)
        float4 o;
        o.x = acc[i][0] * vr; o.y = acc[i][1] * vr;
        o.z = acc[i][2] * vr; o.w = acc[i][3] * vr;
        *(float4*)&g_rec[(size_t)row * HID + tx * 4] = o;
        s[0] += o.x; s[1] += o.y; s[2] += o.z; s[3] += o.w;
        s2[0] += o.x * o.x; s2[1] += o.y * o.y; s2[2] += o.z * o.z; s2[3] += o.w * o.w;
    }
#pragma unroll
    for (int c = 0; c < 4; c++) {
        atomicAdd(&g_stats[tx * 4 + c], s[c]);
        atomicAdd(&g_stats[HID + tx * 4 + c], s2[c]);
    }
}

// ---------------- BN finalize: fold gamma/beta/mean/var into per-column affine ----------------
__global__ void bn_finalize(const float* __restrict__ gamma, const float* __restrict__ beta) {
    int j = threadIdx.x;
    float mean = g_stats[j] * (1.0f / N_VARS);
    float var = g_stats[HID + j] * (1.0f / N_VARS) - mean * mean;
    float a = gamma[j] * rsqrtf(var + BN_EPS);
    g_bnA[j] = a;
    g_bnB[j] = beta[j] - mean * a;
}

// ---------------- GEMM2 + LSTM: gates = [BN(rec) | h] @ Wp2, fused pointwise ----------------
__global__ void __launch_bounds__(256) gates_gemm(const float* __restrict__ hin,
                                                  float* __restrict__ hout) {
    __shared__ __align__(16) float Xs[64][32];
    __shared__ __align__(16) float Ws[32][128];
    const int tid = threadIdx.x;
    const int tx = tid & 31, ty = tid >> 5;
    const int rowBase = blockIdx.x * 64;
    const int jBase = blockIdx.y * 32;
    float acc[8][4];
#pragma unroll
    for (int i = 0; i < 8; i++)
#pragma unroll
        for (int c = 0; c < 4; c++) acc[i][c] = 0.f;

    for (int k0 = 0; k0 < 256; k0 += 32) {
#pragma unroll
        for (int t = tid; t < 512; t += 256) {
            int r = t >> 3, kq = t & 7;
            int row = rowBase + r;
            int gk = k0 + kq * 4;
            float4 v;
            if (gk < HID) {
                v = *(const float4*)&g_rec[(size_t)row * HID + gk];
                float4 a = *(const float4*)&g_bnA[gk];
                float4 b = *(const float4*)&g_bnB[gk];
                v.x = fmaf(v.x, a.x, b.x); v.y = fmaf(v.y, a.y, b.y);
                v.z = fmaf(v.z, a.z, b.z); v.w = fmaf(v.w, a.w, b.w);
            } else {
                v = *(const float4*)&hin[(size_t)row * HID + (gk - HID)];
            }
            *(float4*)&Xs[r][kq * 4] = v;
        }
#pragma unroll
        for (int t = tid; t < 1024; t += 256) {
            int kk = t >> 5, jq = t & 31;
            *(float4*)&Ws[kk][jq * 4] =
                *(const float4*)&g_Wp2[(size_t)(k0 + kk) * 512 + jBase * 4 + jq * 4];
        }
        __syncthreads();
#pragma unroll
        for (int kq = 0; kq < 8; ++kq) {
            float4 w0 = *(float4*)&Ws[kq * 4 + 0][tx * 4];
            float4 w1 = *(float4*)&Ws[kq * 4 + 1][tx * 4];
            float4 w2 = *(float4*)&Ws[kq * 4 + 2][tx * 4];
            float4 w3 = *(float4*)&Ws[kq * 4 + 3][tx * 4];
#pragma unroll
            for (int i = 0; i < 8; ++i) {
                float4 x = *(float4*)&Xs[ty * 8 + i][kq * 4];
                acc[i][0] = fmaf(x.x, w0.x, fmaf(x.y, w1.x, fmaf(x.z, w2.x, fmaf(x.w, w3.x, acc[i][0]))));
                acc[i][1] = fmaf(x.x, w0.y, fmaf(x.y, w1.y, fmaf(x.z, w2.y, fmaf(x.w, w3.y, acc[i][1]))));
                acc[i][2] = fmaf(x.x, w0.z, fmaf(x.y, w1.z, fmaf(x.z, w2.z, fmaf(x.w, w3.z, acc[i][2]))));
                acc[i][3] = fmaf(x.x, w0.w, fmaf(x.y, w1.w, fmaf(x.z, w2.w, fmaf(x.w, w3.w, acc[i][3]))));
            }
        }
        __syncthreads();
    }
    // fused LSTM pointwise epilogue (acc[.][0..3] = i,f,g,o for column j)
    int j = jBase + tx;
    float bi = g_bias[j], bf = g_bias[HID + j], bg = g_bias[2 * HID + j], bo = g_bias[3 * HID + j];
#pragma unroll
    for (int i = 0; i < 8; i++) {
        int row = rowBase + ty * 8 + i;
        size_t idx = (size_t)row * HID + j;
        float ig = acc[i][0] + bi;
        float fg = acc[i][1] + bf;
        float gg = acc[i][2] + bg;
        float og = acc[i][3] + bo;
        float cold = g_c[idx];
        float cn = sigf(fg) * cold + sigf(ig) * tanhf(gg);
        g_c[idx] = cn;
        hout[idx] = sigf(og) * tanhf(cn);
    }
}

// ---------------- output: softmax(h @ W_out^T) ----------------
__global__ void out_kernel(const float* __restrict__ hin,
                           const float* __restrict__ W_out,
                           float* __restrict__ out) {
    int v = (blockIdx.x * blockDim.x + threadIdx.x) >> 5;
    int lane = threadIdx.x & 31;
    if (v >= N_VARS) return;
    float p0 = 0.f, p1 = 0.f, p2 = 0.f;
#pragma unroll
    for (int q = 0; q < 4; q++) {
        int col = lane + q * 32;
        float hv = hin[(size_t)v * HID + col];
        p0 = fmaf(hv, __ldg(&W_out[col]), p0);
        p1 = fmaf(hv, __ldg(&W_out[HID + col]), p1);
        p2 = fmaf(hv, __ldg(&W_out[2 * HID + col]), p2);
    }
#pragma unroll
    for (int o = 16; o > 0; o >>= 1) {
        p0 += __shfl_xor_sync(0xffffffffu, p0, o);
        p1 += __shfl_xor_sync(0xffffffffu, p1, o);
        p2 += __shfl_xor_sync(0xffffffffu, p2, o);
    }
    if (lane == 0) {
        float m = fmaxf(p0, fmaxf(p1, p2));
        float e0 = expf(p0 - m), e1 = expf(p1 - m), e2 = expf(p2 - m);
        float inv = 1.f / (e0 + e1 + e2);
        out[v * 3 + 0] = e0 * inv;
        out[v * 3 + 1] = e1 * inv;
        out[v * 3 + 2] = e2 * inv;
    }
}

// ---------------- launch ----------------
extern "C" void kernel_launch(void* const* d_in, const int* in_sizes, int n_in,
                              void* d_out, int out_size) {
    const float* h0      = (const float*)d_in[0];
    const float* var_reg = (const float*)d_in[1];
    const float* W_msg   = (const float*)d_in[2];
    const float* gamma   = (const float*)d_in[3];
    const float* beta    = (const float*)d_in[4];
    const float* W_ih    = (const float*)d_in[5];
    const float* W_hh    = (const float*)d_in[6];
    const float* b_ih    = (const float*)d_in[7];
    const float* b_hh    = (const float*)d_in[8];
    const float* W_out   = (const float*)d_in[9];
    const int*   ei      = (const int*)d_in[10];
    (void)in_sizes; (void)n_in;

    float *hA, *hB, *cbuf, *agg, *deg, *stats;
    cudaGetSymbolAddress((void**)&hA, g_hA);
    cudaGetSymbolAddress((void**)&hB, g_hB);
    cudaGetSymbolAddress((void**)&cbuf, g_c);
    cudaGetSymbolAddress((void**)&agg, g_agg);
    cudaGetSymbolAddress((void**)&deg, g_degf);
    cudaGetSymbolAddress((void**)&stats, g_stats);

    cudaStream_t s = 0;
    cudaMemcpyAsync(hA, h0, (size_t)N_VARS * HID * sizeof(float),
                    cudaMemcpyDeviceToDevice, s);
    cudaMemsetAsync(hA + (size_t)N_VARS * HID, 0,
                    (size_t)(NP - N_VARS) * HID * sizeof(float), s);
    cudaMemsetAsync(cbuf, 0, (size_t)NP * HID * sizeof(float), s);
    cudaMemsetAsync(deg, 0, (size_t)NP * sizeof(float), s);

    prep_kernel<<<512, 256, 0, s>>>(W_msg, W_ih, W_hh, b_ih, b_hh);
    deg_kernel<<<(2 * N_EDGES + 255) / 256, 256, 0, s>>>(ei);

    const float* hin = hA;
    float* hout = hB;
    for (int st = 0; st < STEPS; ++st) {
        cudaMemsetAsync(agg, 0, (size_t)NP * HID * sizeof(float), s);
        cudaMemsetAsync(stats, 0, 2 * HID * sizeof(float), s);
        agg_kernel<<<N_EDGES / 8, 256, 0, s>>>(ei, hin);
        rec_gemm<<<NP / 64, 256, 0, s>>>(hin, var_reg);
        bn_finalize<<<1, HID, 0, s>>>(gamma, beta);
        gates_gemm<<<dim3(NP / 64, 4), 256, 0, s>>>(hin, hout);
        const float* tmp = hout;
        hout = (float*)hin;
        hin = tmp;
    }
    out_kernel<<<(N_VARS * 32 + 255) / 256, 256, 0, s>>>(hin, W_out, (float*)d_out);
}